// round 7
// baseline (speedup 1.0000x reference)
#include <cuda_runtime.h>
#include <math.h>

#define B_  16
#define S_  1024
#define E_  8192
#define D_  512
#define H_  8
#define DK_ 64
#define L_  2
#define N_  (B_ * S_)          // 16384
#define BE_ (B_ * E_)          // 131072
#define ND_ (N_ * D_)          // 8388608
#define N_DEPREL 50
#define N_DEPARC 3
#define N_RELPOS 21
#define REPS_ELEMS ((size_t)L_ * N_ * D_)       // 16777216
#define ATTN_ELEMS ((size_t)L_ * BE_ * H_)      // 2097152

// ---------------- scratch (device globals; no cudaMalloc allowed) ----------
__device__ float g_h[ND_];
__device__ float g_q[ND_];
__device__ float g_k[ND_];
__device__ float g_v[ND_];
__device__ float g_agg[ND_];
__device__ float g_tmp[ND_];
__device__ float g_logit[BE_ * H_];
__device__ float g_e[BE_ * H_];
__device__ float g_m[N_ * H_];
__device__ float g_denom[N_ * H_];
__device__ int   g_src[BE_];
__device__ int   g_tgt[BE_];
__device__ int   g_dr[BE_];
__device__ int   g_da[BE_];
__device__ int   g_rp[BE_];
__device__ int   g_starts[B_ + 1];

__device__ __forceinline__ int iclamp(int v, int lo, int hi) {
    return v < lo ? lo : (v > hi ? hi : v);
}

__device__ __forceinline__ void atomicMaxFloat(float* addr, float val) {
    int* ia = (int*)addr;
    int old = *ia;
    while (__int_as_float(old) < val) {
        int assumed = old;
        old = atomicCAS(ia, assumed, __float_as_int(val));
        if (old == assumed) break;
    }
}

// ---------------- edge preprocessing ----------------
// sent_len is all 1024; edge_len values lie in [E/2, E]. Pick whichever is
// NOT all-1024.
__global__ void k_starts(const int* __restrict__ lenA, const int* __restrict__ lenB) {
    if (threadIdx.x == 0) {
        const int* el = (lenA[0] == S_) ? lenB : lenA;
        int acc = 0;
        for (int b = 0; b < B_; b++) {
            int v = iclamp(el[b], 0, E_);
            g_starts[b] = acc; acc += v;
        }
        g_starts[B_] = acc;
    }
}

__global__ void k_flatten(const int* __restrict__ lenA, const int* __restrict__ lenB,
                          const int* __restrict__ edge_index,
                          const int* __restrict__ deprel,
                          const int* __restrict__ deparc,
                          const int* __restrict__ relpos_idx) {
    int idx = blockIdx.x * blockDim.x + threadIdx.x;
    if (idx >= BE_) return;
    int b = idx >> 13;          // /E_
    int e = idx & (E_ - 1);
    const int* el = (lenA[0] == S_) ? lenB : lenA;
    int len = iclamp(el[b], 0, E_);
    if (e < len) {
        int p = g_starts[b] + e;
        if (p >= 0 && p < BE_) {
            g_src[p] = iclamp(edge_index[idx * 2 + 0], 0, S_ - 1) + b * S_;
            g_tgt[p] = iclamp(edge_index[idx * 2 + 1], 0, S_ - 1) + b * S_;
            g_dr[p]  = iclamp(deprel[idx], 0, N_DEPREL - 1);
            g_da[p]  = iclamp(deparc[idx], 0, N_DEPARC - 1);
            g_rp[p]  = iclamp(relpos_idx[idx], 0, N_RELPOS - 1);
        }
    }
}

__global__ void k_copy_h(const float* __restrict__ inp, float* __restrict__ h) {
    int idx = blockIdx.x * blockDim.x + threadIdx.x;
    if (idx < ND_) h[idx] = inp[idx];
}

__global__ void k_zero_attn(float* __restrict__ out_attn) {
    int idx = blockIdx.x * blockDim.x + threadIdx.x;
    if (idx < (int)ATTN_ELEMS) out_attn[idx] = 0.0f;
}

__global__ void k_init_seg() {
    int idx = blockIdx.x * blockDim.x + threadIdx.x;
    if (idx < ND_) g_agg[idx] = 0.0f;
    if (idx < N_ * H_) { g_m[idx] = -1e30f; g_denom[idx] = 0.0f; }
}

// ---------------- GEMM: C[M,Nc] = A[M,K] @ Bm[K,Nc] (+ residual) ----------
// 128x128 block tile, K-step 8, 256 threads, 8x8 per-thread microtile.
__global__ __launch_bounds__(256)
void k_gemm(const float* __restrict__ A, const float* __restrict__ Bm,
            const float* __restrict__ residual, float* __restrict__ C,
            int M, int Nc, int K) {
    __shared__ float As[8][128];
    __shared__ float Bs[8][128];
    int tid  = threadIdx.x;
    int brow = blockIdx.y * 128;
    int bcol = blockIdx.x * 128;
    int ty = tid >> 4, tx = tid & 15;

    int arow = tid >> 1, acol = (tid & 1) * 4;
    int brs  = tid >> 5, bcs  = (tid & 31) * 4;

    float acc[8][8];
#pragma unroll
    for (int i = 0; i < 8; i++)
#pragma unroll
        for (int j = 0; j < 8; j++) acc[i][j] = 0.0f;

    for (int k0 = 0; k0 < K; k0 += 8) {
        float4 av = *(const float4*)(A + (size_t)(brow + arow) * K + k0 + acol);
        As[acol + 0][arow] = av.x;
        As[acol + 1][arow] = av.y;
        As[acol + 2][arow] = av.z;
        As[acol + 3][arow] = av.w;
        float4 bv = *(const float4*)(Bm + (size_t)(k0 + brs) * Nc + bcol + bcs);
        *(float4*)&Bs[brs][bcs] = bv;
        __syncthreads();
#pragma unroll
        for (int kk = 0; kk < 8; kk++) {
            float4 a0 = *(const float4*)&As[kk][ty * 4];
            float4 a1 = *(const float4*)&As[kk][64 + ty * 4];
            float4 b0 = *(const float4*)&Bs[kk][tx * 4];
            float4 b1 = *(const float4*)&Bs[kk][64 + tx * 4];
            float a[8] = {a0.x, a0.y, a0.z, a0.w, a1.x, a1.y, a1.z, a1.w};
            float b[8] = {b0.x, b0.y, b0.z, b0.w, b1.x, b1.y, b1.z, b1.w};
#pragma unroll
            for (int i = 0; i < 8; i++)
#pragma unroll
                for (int j = 0; j < 8; j++) acc[i][j] += a[i] * b[j];
        }
        __syncthreads();
    }
#pragma unroll
    for (int ii = 0; ii < 2; ii++)
#pragma unroll
        for (int i = 0; i < 4; i++) {
            int r = brow + ii * 64 + ty * 4 + i;
#pragma unroll
            for (int jj = 0; jj < 2; jj++) {
                int c = bcol + jj * 64 + tx * 4;
                float4 res;
                res.x = acc[ii * 4 + i][jj * 4 + 0];
                res.y = acc[ii * 4 + i][jj * 4 + 1];
                res.z = acc[ii * 4 + i][jj * 4 + 2];
                res.w = acc[ii * 4 + i][jj * 4 + 3];
                if (residual) {
                    const float4 rv = *(const float4*)(residual + (size_t)r * Nc + c);
                    res.x += rv.x; res.y += rv.y; res.z += rv.z; res.w += rv.w;
                }
                *(float4*)(C + (size_t)r * Nc + c) = res;
            }
        }
}

// ---------------- edge logit + segment max --------------------------------
__global__ __launch_bounds__(256)
void k_logit(const float* __restrict__ deprel_emb,
             const float* __restrict__ deparc_emb,
             const float* __restrict__ relpos_emb) {
    int warp = (blockIdx.x * blockDim.x + threadIdx.x) >> 5;
    int lane = threadIdx.x & 31;
    int etot = iclamp(g_starts[B_], 0, BE_);
    if (warp >= etot) return;
    int p = warp;
    int s = g_src[p], t = g_tgt[p];
    const float* e1 = deprel_emb + (size_t)g_dr[p] * DK_;
    const float* e2 = deparc_emb + (size_t)g_da[p] * DK_;
    const float* e3 = relpos_emb + (size_t)g_rp[p] * DK_;
    float rel0 = e1[lane]      + e2[lane]      + e3[lane];
    float rel1 = e1[lane + 32] + e2[lane + 32] + e3[lane + 32];
    const float* qb = g_q + (size_t)t * D_;
    const float* kb = g_k + (size_t)s * D_;
#pragma unroll
    for (int h = 0; h < H_; h++) {
        float part = qb[h * DK_ + lane]      * (kb[h * DK_ + lane]      + rel0)
                   + qb[h * DK_ + lane + 32] * (kb[h * DK_ + lane + 32] + rel1);
#pragma unroll
        for (int off = 16; off > 0; off >>= 1)
            part += __shfl_xor_sync(0xFFFFFFFFu, part, off);
        if (lane == 0) {
            float lg = part * 0.125f;   // 1/sqrt(64)
            g_logit[p * H_ + h] = lg;
            atomicMaxFloat(&g_m[t * H_ + h], lg);
        }
    }
}

// ---------------- exp + segment sum ---------------------------------------
__global__ void k_exp() {
    int idx = blockIdx.x * blockDim.x + threadIdx.x;
    if (idx >= BE_ * H_) return;
    int p = idx >> 3;
    int etot = iclamp(g_starts[B_], 0, BE_);
    if (p >= etot) return;
    int h = idx & 7;
    int t = g_tgt[p];
    float ev = expf(g_logit[idx] - g_m[t * H_ + h]);
    g_e[idx] = ev;
    atomicAdd(&g_denom[t * H_ + h], ev);
}

// ---------------- alpha + message scatter ---------------------------------
__global__ __launch_bounds__(256)
void k_msg(const float* __restrict__ deprel_emb,
           const float* __restrict__ deparc_emb,
           const float* __restrict__ relpos_emb,
           float* __restrict__ out_attn, int write_attn) {
    int warp = (blockIdx.x * blockDim.x + threadIdx.x) >> 5;
    int lane = threadIdx.x & 31;
    int etot = iclamp(g_starts[B_], 0, BE_);
    if (warp >= etot) return;
    int p = warp;
    int s = g_src[p], t = g_tgt[p];
    float alpha = 0.0f;
    if (lane < H_) {
        alpha = g_e[p * H_ + lane] / (g_denom[t * H_ + lane] + 1e-9f);
        if (write_attn) out_attn[p * H_ + lane] = alpha;
    }
    const float* e1 = deprel_emb + (size_t)g_dr[p] * DK_;
    const float* e2 = deparc_emb + (size_t)g_da[p] * DK_;
    const float* e3 = relpos_emb + (size_t)g_rp[p] * DK_;
    float rel0 = e1[lane]      + e2[lane]      + e3[lane];
    float rel1 = e1[lane + 32] + e2[lane + 32] + e3[lane + 32];
    const float* vb = g_v + (size_t)s * D_;
    float* ab = g_agg + (size_t)t * D_;
#pragma unroll
    for (int h = 0; h < H_; h++) {
        float a = __shfl_sync(0xFFFFFFFFu, alpha, h);
        atomicAdd(&ab[h * DK_ + lane],      a * (vb[h * DK_ + lane]      + rel0));
        atomicAdd(&ab[h * DK_ + lane + 32], a * (vb[h * DK_ + lane + 32] + rel1));
    }
}

// ---------------- layernorm (+ optional relu), write reps + next h --------
__global__ __launch_bounds__(256)
void k_ln(const float* __restrict__ x, const float* __restrict__ scale,
          const float* __restrict__ bias, float* __restrict__ out_reps,
          float* __restrict__ h_next, int do_relu, int write_reps) {
    __shared__ float red[256];
    int row = blockIdx.x;
    int t = threadIdx.x;
    const float* xr = x + (size_t)row * D_;
    float x0 = xr[t], x1 = xr[t + 256];

    red[t] = x0 + x1;
    __syncthreads();
    for (int s = 128; s > 0; s >>= 1) {
        if (t < s) red[t] += red[t + s];
        __syncthreads();
    }
    float mu = red[0] * (1.0f / D_);
    __syncthreads();

    float d0 = x0 - mu, d1 = x1 - mu;
    red[t] = d0 * d0 + d1 * d1;
    __syncthreads();
    for (int s = 128; s > 0; s >>= 1) {
        if (t < s) red[t] += red[t + s];
        __syncthreads();
    }
    float inv = rsqrtf(red[0] * (1.0f / D_) + 1e-5f);

    float y0 = d0 * inv * scale[t] + bias[t];
    float y1 = d1 * inv * scale[t + 256] + bias[t + 256];
    if (do_relu) { y0 = fmaxf(y0, 0.0f); y1 = fmaxf(y1, 0.0f); }
    if (write_reps) {
        out_reps[(size_t)row * D_ + t]       = y0;
        out_reps[(size_t)row * D_ + t + 256] = y1;
    }
    h_next[(size_t)row * D_ + t]       = y0;
    h_next[(size_t)row * D_ + t + 256] = y1;
}

// ---------------- launch ----------------
extern "C" void kernel_launch(void* const* d_in, const int* in_sizes, int n_in,
                              void* d_out, int out_size) {
    // Input-index maps for the two plausible metadata orderings.
    int I_inp = 0, I_lenA = 2, I_lenB = 1, I_ei = 3, I_rp = 4, I_dr = 6, I_da = 7;
    int I_Wq = 14, I_Wk = 15, I_Wv = 16, I_Wo = 17;
    int I_dre = 18, I_dae = 19, I_rpe = 20, I_lns = 21, I_lnb = 22;
    if (n_in >= 23 && in_sizes[0] != ND_) {
        // sorted-key (alphabetical) order
        I_inp = 16; I_lenA = 15; I_lenB = 21; I_ei = 14; I_rp = 4; I_dr = 8; I_da = 5;
        I_Wq = 2; I_Wk = 0; I_Wv = 3; I_Wo = 1;
        I_dre = 9; I_dae = 6; I_rpe = 20; I_lns = 18; I_lnb = 17;
    }

    const float* inp        = (const float*)d_in[I_inp];
    const int*   lenA       = (const int*)d_in[I_lenA];
    const int*   lenB       = (const int*)d_in[I_lenB];
    const int*   edge_index = (const int*)d_in[I_ei];
    const int*   relpos_idx = (const int*)d_in[I_rp];
    const int*   deprel     = (const int*)d_in[I_dr];
    const int*   deparc     = (const int*)d_in[I_da];
    const float* Wq         = (const float*)d_in[I_Wq];
    const float* Wk         = (const float*)d_in[I_Wk];
    const float* Wv         = (const float*)d_in[I_Wv];
    const float* Wo         = (const float*)d_in[I_Wo];
    const float* deprel_emb = (const float*)d_in[I_dre];
    const float* deparc_emb = (const float*)d_in[I_dae];
    const float* relpos_emb = (const float*)d_in[I_rpe];
    const float* ln_scale   = (const float*)d_in[I_lns];
    const float* ln_bias    = (const float*)d_in[I_lnb];

    // CRITICAL: __device__ symbols are NOT valid device pointers in host code.
    // On GB300 (ATS) passing them as kernel args silently reads/writes the
    // host-side shadow instead of faulting. Fetch real device addresses.
    static float *p_h = 0, *p_q = 0, *p_k = 0, *p_v = 0, *p_agg = 0, *p_tmp = 0;
    if (!p_h) {
        void* pv;
        cudaGetSymbolAddress(&pv, g_h);   p_h   = (float*)pv;
        cudaGetSymbolAddress(&pv, g_q);   p_q   = (float*)pv;
        cudaGetSymbolAddress(&pv, g_k);   p_k   = (float*)pv;
        cudaGetSymbolAddress(&pv, g_v);   p_v   = (float*)pv;
        cudaGetSymbolAddress(&pv, g_agg); p_agg = (float*)pv;
        cudaGetSymbolAddress(&pv, g_tmp); p_tmp = (float*)pv;
    }

    float* out = (float*)d_out;
    float* out_reps = out;                                  // (L,B,S,D)
    float* out_attn = out + REPS_ELEMS;                     // (L,BE,H)
    int write_reps = (out_size >= (int)REPS_ELEMS) ? 1 : 0;
    int write_attn = (out_size >= (int)(REPS_ELEMS + ATTN_ELEMS)) ? 1 : 0;

    k_starts<<<1, 32>>>(lenA, lenB);
    k_flatten<<<BE_ / 256, 256>>>(lenA, lenB, edge_index, deprel, deparc, relpos_idx);
    k_copy_h<<<ND_ / 256, 256>>>(inp, p_h);
    if (write_attn)
        k_zero_attn<<<(int)(ATTN_ELEMS / 256), 256>>>(out_attn);

    dim3 gemm_grid(D_ / 128, N_ / 128);   // (4, 128)

    for (int l = 0; l < L_; l++) {
        const float* wq = Wq + (size_t)l * D_ * D_;
        const float* wk = Wk + (size_t)l * D_ * D_;
        const float* wv = Wv + (size_t)l * D_ * D_;
        const float* wo = Wo + (size_t)l * D_ * D_;
        const float* de = deprel_emb + (size_t)l * N_DEPREL * DK_;
        const float* da = deparc_emb + (size_t)l * N_DEPARC * DK_;
        const float* re = relpos_emb + (size_t)l * N_RELPOS * DK_;

        k_gemm<<<gemm_grid, 256>>>(p_h, wq, 0, p_q, N_, D_, D_);
        k_gemm<<<gemm_grid, 256>>>(p_h, wk, 0, p_k, N_, D_, D_);
        k_gemm<<<gemm_grid, 256>>>(p_h, wv, 0, p_v, N_, D_, D_);
        k_init_seg<<<ND_ / 256, 256>>>();
        k_logit<<<BE_ / 8, 256>>>(de, da, re);
        k_exp<<<(BE_ * H_) / 256, 256>>>();
        k_msg<<<BE_ / 8, 256>>>(de, da, re, out_attn + (size_t)l * BE_ * H_, write_attn);
        k_gemm<<<gemm_grid, 256>>>(p_agg, wo, p_h, p_tmp, N_, D_, D_);
        k_ln<<<N_, 256>>>(p_tmp, ln_scale + (size_t)l * D_, ln_bias + (size_t)l * D_,
                          out_reps + (size_t)l * N_ * D_, p_h,
                          (l < L_ - 1) ? 1 : 0, write_reps);
    }
    (void)in_sizes; (void)n_in; (void)out_size;
}

// round 14
// speedup vs baseline: 1.3949x; 1.3949x over previous
#include <cuda_runtime.h>
#include <cuda_bf16.h>
#include <math.h>
#include <stdint.h>

#define B_  16
#define S_  1024
#define E_  8192
#define D_  512
#define H_  8
#define DK_ 64
#define L_  2
#define N_  (B_ * S_)          // 16384
#define BE_ (B_ * E_)          // 131072
#define ND_ (N_ * D_)          // 8388608
#define K3_ 1536               // 3x split K
#define N_DEPREL 50
#define N_DEPARC 3
#define N_RELPOS 21
#define REPS_ELEMS ((size_t)L_ * N_ * D_)       // 16777216
#define ATTN_ELEMS ((size_t)L_ * BE_ * H_)      // 2097152

// ---------------- scratch (device globals; no cudaMalloc allowed) ----------
__device__ float g_h[ND_];
__device__ float g_q[ND_];
__device__ float g_k[ND_];
__device__ float g_v[ND_];
__device__ float g_agg[ND_];
__device__ float g_tmp[ND_];
__device__ float g_logit[BE_ * H_];
__device__ float g_e[BE_ * H_];
__device__ float g_m[N_ * H_];
__device__ float g_denom[N_ * H_];
__device__ int   g_src[BE_];
__device__ int   g_tgt[BE_];
__device__ int   g_dr[BE_];
__device__ int   g_da[BE_];
__device__ int   g_rp[BE_];
__device__ int   g_starts[B_ + 1];
__device__ __nv_bfloat16 g_ahh[(size_t)N_ * K3_];   // [hi | hi | lo]
__device__ __nv_bfloat16 g_wt[(size_t)D_ * K3_];    // transposed [hi ; lo ; hi]

// ---------------- misc helpers ----------------
__device__ __forceinline__ int iclamp(int v, int lo, int hi) {
    return v < lo ? lo : (v > hi ? hi : v);
}
__device__ __forceinline__ void atomicMaxFloat(float* addr, float val) {
    int* ia = (int*)addr;
    int old = *ia;
    while (__int_as_float(old) < val) {
        int assumed = old;
        old = atomicCAS(ia, assumed, __float_as_int(val));
        if (old == assumed) break;
    }
}
__device__ __forceinline__ uint32_t pack_bf2(__nv_bfloat16 a, __nv_bfloat16 b) {
    __nv_bfloat162 p(a, b);
    return *(uint32_t*)&p;
}

// ---------------- edge preprocessing ----------------
__global__ void k_starts(const int* __restrict__ lenA, const int* __restrict__ lenB) {
    if (threadIdx.x == 0) {
        const int* el = (lenA[0] == S_) ? lenB : lenA;
        int acc = 0;
        for (int b = 0; b < B_; b++) {
            int v = iclamp(el[b], 0, E_);
            g_starts[b] = acc; acc += v;
        }
        g_starts[B_] = acc;
    }
}

__global__ void k_flatten(const int* __restrict__ lenA, const int* __restrict__ lenB,
                          const int* __restrict__ edge_index,
                          const int* __restrict__ deprel,
                          const int* __restrict__ deparc,
                          const int* __restrict__ relpos_idx) {
    int idx = blockIdx.x * blockDim.x + threadIdx.x;
    if (idx >= BE_) return;
    int b = idx >> 13;
    int e = idx & (E_ - 1);
    const int* el = (lenA[0] == S_) ? lenB : lenA;
    int len = iclamp(el[b], 0, E_);
    if (e < len) {
        int p = g_starts[b] + e;
        if (p >= 0 && p < BE_) {
            g_src[p] = iclamp(edge_index[idx * 2 + 0], 0, S_ - 1) + b * S_;
            g_tgt[p] = iclamp(edge_index[idx * 2 + 1], 0, S_ - 1) + b * S_;
            g_dr[p]  = iclamp(deprel[idx], 0, N_DEPREL - 1);
            g_da[p]  = iclamp(deparc[idx], 0, N_DEPARC - 1);
            g_rp[p]  = iclamp(relpos_idx[idx], 0, N_RELPOS - 1);
        }
    }
}

__global__ void k_zero_attn(float* __restrict__ out_attn) {
    int idx = blockIdx.x * blockDim.x + threadIdx.x;
    if (idx < (int)ATTN_ELEMS) out_attn[idx] = 0.0f;
}

__global__ void k_init_seg() {
    int idx = blockIdx.x * blockDim.x + threadIdx.x;
    if (idx < ND_) g_agg[idx] = 0.0f;
    if (idx < N_ * H_) { g_m[idx] = -1e30f; g_denom[idx] = 0.0f; }
}

// ---------------- bf16 hi/lo split conversions ----------------------------
// A (rows x 512 fp32) -> Ahh (rows x 1536 bf16) = [hi | hi | lo], float4-vectorized
__global__ void k_cvt_A(const float* __restrict__ src, __nv_bfloat16* __restrict__ dst) {
    int i = blockIdx.x * blockDim.x + threadIdx.x;
    if (i >= ND_ / 4) return;
    int row = i >> 7;           // 128 quads per 512-col row
    int q = (i & 127) * 4;
    float4 a = *(const float4*)(src + (size_t)row * D_ + q);
    __nv_bfloat16 h0 = __float2bfloat16(a.x), h1 = __float2bfloat16(a.y);
    __nv_bfloat16 h2 = __float2bfloat16(a.z), h3 = __float2bfloat16(a.w);
    __nv_bfloat16 l0 = __float2bfloat16(a.x - __bfloat162float(h0));
    __nv_bfloat16 l1 = __float2bfloat16(a.y - __bfloat162float(h1));
    __nv_bfloat16 l2 = __float2bfloat16(a.z - __bfloat162float(h2));
    __nv_bfloat16 l3 = __float2bfloat16(a.w - __bfloat162float(h3));
    uint2 hw, lw;
    hw.x = pack_bf2(h0, h1); hw.y = pack_bf2(h2, h3);
    lw.x = pack_bf2(l0, l1); lw.y = pack_bf2(l2, l3);
    size_t b = (size_t)row * K3_;
    *(uint2*)(dst + b + q)        = hw;
    *(uint2*)(dst + b + 512 + q)  = hw;
    *(uint2*)(dst + b + 1024 + q) = lw;
}

// W (512k x 512n fp32, k-major) -> Wt (512n x 1536 bf16) = [hi ; lo ; hi] along k3
__global__ void k_cvt_W(const float* __restrict__ W, __nv_bfloat16* __restrict__ dst) {
    int i = blockIdx.x * blockDim.x + threadIdx.x;
    if (i >= D_ * D_) return;
    int k = i >> 9, n = i & 511;
    float w = W[i];
    __nv_bfloat16 hi = __float2bfloat16(w);
    __nv_bfloat16 lo = __float2bfloat16(w - __bfloat162float(hi));
    size_t b = (size_t)n * K3_;
    dst[b + k] = hi;
    dst[b + 512 + k] = lo;
    dst[b + 1024 + k] = hi;
}

// ---------------- mma.sync bf16 GEMM: C[16384,512] = Ahh @ Wt^T (+resid) ---
// CTA 128x128, 8 warps (2m x 4n), warp tile 64x32, K-chunk 32, double buffer.
// SMEM rows padded to 40 bf16 (20 words): fragment LDS pattern is bank-free.
#define KC_ 32
#define NCH_ (K3_ / KC_)       // 48
#define ROWW_ 20               // words per smem row (40 bf16)

#define MMA_BF16(d, a0, a1, a2, a3, b0, b1)                                   \
    asm volatile(                                                             \
        "mma.sync.aligned.m16n8k16.row.col.f32.bf16.bf16.f32 "                \
        "{%0,%1,%2,%3}, {%4,%5,%6,%7}, {%8,%9}, {%0,%1,%2,%3};"               \
        : "+f"((d)[0]), "+f"((d)[1]), "+f"((d)[2]), "+f"((d)[3])              \
        : "r"(a0), "r"(a1), "r"(a2), "r"(a3), "r"(b0), "r"(b1))

__global__ __launch_bounds__(256)
void k_mma_gemm(const __nv_bfloat16* __restrict__ A,
                const __nv_bfloat16* __restrict__ Bt,
                const float* __restrict__ residual,
                float* __restrict__ C) {
    __shared__ __align__(16) uint32_t As[2][128 * ROWW_];
    __shared__ __align__(16) uint32_t Bs[2][128 * ROWW_];

    int tid = threadIdx.x;
    int warp = tid >> 5, lane = tid & 31;
    int gid = lane >> 2, tig = lane & 3;
    int wm = warp >> 2, wn = warp & 3;          // 2 x 4 warp grid
    int m0 = blockIdx.y * 128;
    int n0 = blockIdx.x * 128;

    // global->smem mapping: u in [0,512): row=u/4, grp=u%4 (8 bf16 each)
    int uA0 = tid, uA1 = tid + 256;
    int rA0 = uA0 >> 2, gA0 = uA0 & 3;
    int rA1 = uA1 >> 2, gA1 = uA1 & 3;

    float acc[4][4][4];
#pragma unroll
    for (int i = 0; i < 4; i++)
#pragma unroll
        for (int j = 0; j < 4; j++)
#pragma unroll
            for (int r = 0; r < 4; r++) acc[i][j][r] = 0.0f;

    const __nv_bfloat16* Abase = A + (size_t)m0 * K3_;
    const __nv_bfloat16* Bbase = Bt + (size_t)n0 * K3_;

    uint4 ra0 = *(const uint4*)(Abase + (size_t)rA0 * K3_ + gA0 * 8);
    uint4 ra1 = *(const uint4*)(Abase + (size_t)rA1 * K3_ + gA1 * 8);
    uint4 rb0 = *(const uint4*)(Bbase + (size_t)rA0 * K3_ + gA0 * 8);
    uint4 rb1 = *(const uint4*)(Bbase + (size_t)rA1 * K3_ + gA1 * 8);
    *(uint4*)&As[0][rA0 * ROWW_ + gA0 * 4] = ra0;
    *(uint4*)&As[0][rA1 * ROWW_ + gA1 * 4] = ra1;
    *(uint4*)&Bs[0][rA0 * ROWW_ + gA0 * 4] = rb0;
    *(uint4*)&Bs[0][rA1 * ROWW_ + gA1 * 4] = rb1;
    __syncthreads();

    for (int c = 0; c < NCH_; c++) {
        int buf = c & 1;
        if (c + 1 < NCH_) {
            size_t off = (size_t)(c + 1) * KC_;
            ra0 = *(const uint4*)(Abase + (size_t)rA0 * K3_ + off + gA0 * 8);
            ra1 = *(const uint4*)(Abase + (size_t)rA1 * K3_ + off + gA1 * 8);
            rb0 = *(const uint4*)(Bbase + (size_t)rA0 * K3_ + off + gA0 * 8);
            rb1 = *(const uint4*)(Bbase + (size_t)rA1 * K3_ + off + gA1 * 8);
        }
        // compute on buf
#pragma unroll
        for (int s = 0; s < 2; s++) {
            int kb = s * 8;
            uint32_t bfr[4][2];
#pragma unroll
            for (int nt = 0; nt < 4; nt++) {
                int nr = wn * 32 + nt * 8 + gid;
                bfr[nt][0] = Bs[buf][nr * ROWW_ + kb + tig];
                bfr[nt][1] = Bs[buf][nr * ROWW_ + kb + tig + 4];
            }
#pragma unroll
            for (int mt = 0; mt < 4; mt++) {
                int mr = wm * 64 + mt * 16 + gid;
                uint32_t a0 = As[buf][mr * ROWW_ + kb + tig];
                uint32_t a1 = As[buf][(mr + 8) * ROWW_ + kb + tig];
                uint32_t a2 = As[buf][mr * ROWW_ + kb + tig + 4];
                uint32_t a3 = As[buf][(mr + 8) * ROWW_ + kb + tig + 4];
#pragma unroll
                for (int nt = 0; nt < 4; nt++)
                    MMA_BF16(acc[mt][nt], a0, a1, a2, a3, bfr[nt][0], bfr[nt][1]);
            }
        }
        if (c + 1 < NCH_) {
            int nb = buf ^ 1;
            *(uint4*)&As[nb][rA0 * ROWW_ + gA0 * 4] = ra0;
            *(uint4*)&As[nb][rA1 * ROWW_ + gA1 * 4] = ra1;
            *(uint4*)&Bs[nb][rA0 * ROWW_ + gA0 * 4] = rb0;
            *(uint4*)&Bs[nb][rA1 * ROWW_ + gA1 * 4] = rb1;
        }
        __syncthreads();
    }

    // epilogue
#pragma unroll
    for (int mt = 0; mt < 4; mt++) {
        int r0 = m0 + wm * 64 + mt * 16 + gid;
        int r1 = r0 + 8;
#pragma unroll
        for (int nt = 0; nt < 4; nt++) {
            int cc = n0 + wn * 32 + nt * 8 + tig * 2;
            float2 v0 = make_float2(acc[mt][nt][0], acc[mt][nt][1]);
            float2 v1 = make_float2(acc[mt][nt][2], acc[mt][nt][3]);
            if (residual) {
                float2 q0 = *(const float2*)(residual + (size_t)r0 * D_ + cc);
                float2 q1 = *(const float2*)(residual + (size_t)r1 * D_ + cc);
                v0.x += q0.x; v0.y += q0.y;
                v1.x += q1.x; v1.y += q1.y;
            }
            *(float2*)(C + (size_t)r0 * D_ + cc) = v0;
            *(float2*)(C + (size_t)r1 * D_ + cc) = v1;
        }
    }
}

// ---------------- edge logit + segment max --------------------------------
__global__ __launch_bounds__(256)
void k_logit(const float* __restrict__ deprel_emb,
             const float* __restrict__ deparc_emb,
             const float* __restrict__ relpos_emb) {
    int warp = (blockIdx.x * blockDim.x + threadIdx.x) >> 5;
    int lane = threadIdx.x & 31;
    int etot = iclamp(g_starts[B_], 0, BE_);
    if (warp >= etot) return;
    int p = warp;
    int s = g_src[p], t = g_tgt[p];
    const float* e1 = deprel_emb + (size_t)g_dr[p] * DK_;
    const float* e2 = deparc_emb + (size_t)g_da[p] * DK_;
    const float* e3 = relpos_emb + (size_t)g_rp[p] * DK_;
    float rel0 = e1[lane]      + e2[lane]      + e3[lane];
    float rel1 = e1[lane + 32] + e2[lane + 32] + e3[lane + 32];
    const float* qb = g_q + (size_t)t * D_;
    const float* kb = g_k + (size_t)s * D_;
#pragma unroll
    for (int h = 0; h < H_; h++) {
        float part = qb[h * DK_ + lane]      * (kb[h * DK_ + lane]      + rel0)
                   + qb[h * DK_ + lane + 32] * (kb[h * DK_ + lane + 32] + rel1);
#pragma unroll
        for (int off = 16; off > 0; off >>= 1)
            part += __shfl_xor_sync(0xFFFFFFFFu, part, off);
        if (lane == 0) {
            float lg = part * 0.125f;
            g_logit[p * H_ + h] = lg;
            atomicMaxFloat(&g_m[t * H_ + h], lg);
        }
    }
}

// ---------------- exp + segment sum ---------------------------------------
__global__ void k_exp() {
    int idx = blockIdx.x * blockDim.x + threadIdx.x;
    if (idx >= BE_ * H_) return;
    int p = idx >> 3;
    int etot = iclamp(g_starts[B_], 0, BE_);
    if (p >= etot) return;
    int h = idx & 7;
    int t = g_tgt[p];
    float ev = expf(g_logit[idx] - g_m[t * H_ + h]);
    g_e[idx] = ev;
    atomicAdd(&g_denom[t * H_ + h], ev);
}

// ---------------- alpha + message scatter ---------------------------------
__global__ __launch_bounds__(256)
void k_msg(const float* __restrict__ deprel_emb,
           const float* __restrict__ deparc_emb,
           const float* __restrict__ relpos_emb,
           float* __restrict__ out_attn, int write_attn) {
    int warp = (blockIdx.x * blockDim.x + threadIdx.x) >> 5;
    int lane = threadIdx.x & 31;
    int etot = iclamp(g_starts[B_], 0, BE_);
    if (warp >= etot) return;
    int p = warp;
    int s = g_src[p], t = g_tgt[p];
    float alpha = 0.0f;
    if (lane < H_) {
        alpha = g_e[p * H_ + lane] / (g_denom[t * H_ + lane] + 1e-9f);
        if (write_attn) out_attn[p * H_ + lane] = alpha;
    }
    const float* e1 = deprel_emb + (size_t)g_dr[p] * DK_;
    const float* e2 = deparc_emb + (size_t)g_da[p] * DK_;
    const float* e3 = relpos_emb + (size_t)g_rp[p] * DK_;
    float rel0 = e1[lane]      + e2[lane]      + e3[lane];
    float rel1 = e1[lane + 32] + e2[lane + 32] + e3[lane + 32];
    const float* vb = g_v + (size_t)s * D_;
    float* ab = g_agg + (size_t)t * D_;
#pragma unroll
    for (int h = 0; h < H_; h++) {
        float a = __shfl_sync(0xFFFFFFFFu, alpha, h);
        atomicAdd(&ab[h * DK_ + lane],      a * (vb[h * DK_ + lane]      + rel0));
        atomicAdd(&ab[h * DK_ + lane + 32], a * (vb[h * DK_ + lane + 32] + rel1));
    }
}

// ---------------- layernorm (+ optional relu) -----------------------------
__global__ __launch_bounds__(256)
void k_ln(const float* __restrict__ x, const float* __restrict__ scale,
          const float* __restrict__ bias, float* __restrict__ out_reps,
          float* __restrict__ h_next, int do_relu, int write_reps) {
    __shared__ float red[256];
    int row = blockIdx.x;
    int t = threadIdx.x;
    const float* xr = x + (size_t)row * D_;
    float x0 = xr[t], x1 = xr[t + 256];

    red[t] = x0 + x1;
    __syncthreads();
    for (int s = 128; s > 0; s >>= 1) {
        if (t < s) red[t] += red[t + s];
        __syncthreads();
    }
    float mu = red[0] * (1.0f / D_);
    __syncthreads();

    float d0 = x0 - mu, d1 = x1 - mu;
    red[t] = d0 * d0 + d1 * d1;
    __syncthreads();
    for (int s = 128; s > 0; s >>= 1) {
        if (t < s) red[t] += red[t + s];
        __syncthreads();
    }
    float inv = rsqrtf(red[0] * (1.0f / D_) + 1e-5f);

    float y0 = d0 * inv * scale[t] + bias[t];
    float y1 = d1 * inv * scale[t + 256] + bias[t + 256];
    if (do_relu) { y0 = fmaxf(y0, 0.0f); y1 = fmaxf(y1, 0.0f); }
    if (write_reps) {
        out_reps[(size_t)row * D_ + t]       = y0;
        out_reps[(size_t)row * D_ + t + 256] = y1;
    }
    h_next[(size_t)row * D_ + t]       = y0;
    h_next[(size_t)row * D_ + t + 256] = y1;
}

// ---------------- launch ----------------
extern "C" void kernel_launch(void* const* d_in, const int* in_sizes, int n_in,
                              void* d_out, int out_size) {
    int I_inp = 0, I_lenA = 2, I_lenB = 1, I_ei = 3, I_rp = 4, I_dr = 6, I_da = 7;
    int I_Wq = 14, I_Wk = 15, I_Wv = 16, I_Wo = 17;
    int I_dre = 18, I_dae = 19, I_rpe = 20, I_lns = 21, I_lnb = 22;
    if (n_in >= 23 && in_sizes[0] != ND_) {
        I_inp = 16; I_lenA = 15; I_lenB = 21; I_ei = 14; I_rp = 4; I_dr = 8; I_da = 5;
        I_Wq = 2; I_Wk = 0; I_Wv = 3; I_Wo = 1;
        I_dre = 9; I_dae = 6; I_rpe = 20; I_lns = 18; I_lnb = 17;
    }

    const float* inp        = (const float*)d_in[I_inp];
    const int*   lenA       = (const int*)d_in[I_lenA];
    const int*   lenB       = (const int*)d_in[I_lenB];
    const int*   edge_index = (const int*)d_in[I_ei];
    const int*   relpos_idx = (const int*)d_in[I_rp];
    const int*   deprel     = (const int*)d_in[I_dr];
    const int*   deparc     = (const int*)d_in[I_da];
    const float* Wq         = (const float*)d_in[I_Wq];
    const float* Wk         = (const float*)d_in[I_Wk];
    const float* Wv         = (const float*)d_in[I_Wv];
    const float* Wo         = (const float*)d_in[I_Wo];
    const float* deprel_emb = (const float*)d_in[I_dre];
    const float* deparc_emb = (const float*)d_in[I_dae];
    const float* relpos_emb = (const float*)d_in[I_rpe];
    const float* ln_scale   = (const float*)d_in[I_lns];
    const float* ln_bias    = (const float*)d_in[I_lnb];

    // real device addresses for __device__ symbols (GB300/ATS trap!)
    static float *p_h = 0, *p_q = 0, *p_k = 0, *p_v = 0, *p_agg = 0, *p_tmp = 0;
    static __nv_bfloat16 *p_ahh = 0, *p_wt = 0;
    if (!p_h) {
        void* pv;
        cudaGetSymbolAddress(&pv, g_h);   p_h   = (float*)pv;
        cudaGetSymbolAddress(&pv, g_q);   p_q   = (float*)pv;
        cudaGetSymbolAddress(&pv, g_k);   p_k   = (float*)pv;
        cudaGetSymbolAddress(&pv, g_v);   p_v   = (float*)pv;
        cudaGetSymbolAddress(&pv, g_agg); p_agg = (float*)pv;
        cudaGetSymbolAddress(&pv, g_tmp); p_tmp = (float*)pv;
        cudaGetSymbolAddress(&pv, g_ahh); p_ahh = (__nv_bfloat16*)pv;
        cudaGetSymbolAddress(&pv, g_wt);  p_wt  = (__nv_bfloat16*)pv;
    }

    float* out = (float*)d_out;
    float* out_reps = out;
    float* out_attn = out + REPS_ELEMS;
    int write_reps = (out_size >= (int)REPS_ELEMS) ? 1 : 0;
    int write_attn = (out_size >= (int)(REPS_ELEMS + ATTN_ELEMS)) ? 1 : 0;

    k_starts<<<1, 32>>>(lenA, lenB);
    k_flatten<<<BE_ / 256, 256>>>(lenA, lenB, edge_index, deprel, deparc, relpos_idx);
    if (write_attn)
        k_zero_attn<<<(int)(ATTN_ELEMS / 256), 256>>>(out_attn);

    dim3 mma_grid(D_ / 128, N_ / 128);  // (4, 128)

    for (int l = 0; l < L_; l++) {
        const float* wq = Wq + (size_t)l * D_ * D_;
        const float* wk = Wk + (size_t)l * D_ * D_;
        const float* wv = Wv + (size_t)l * D_ * D_;
        const float* wo = Wo + (size_t)l * D_ * D_;
        const float* de = deprel_emb + (size_t)l * N_DEPREL * DK_;
        const float* da = deparc_emb + (size_t)l * N_DEPARC * DK_;
        const float* re = relpos_emb + (size_t)l * N_RELPOS * DK_;
        const float* hsrc = (l == 0) ? inp : p_h;

        k_cvt_A<<<ND_ / 4 / 256, 256>>>(hsrc, p_ahh);
        k_cvt_W<<<(D_ * D_) / 256, 256>>>(wq, p_wt);
        k_mma_gemm<<<mma_grid, 256>>>(p_ahh, p_wt, 0, p_q);
        k_cvt_W<<<(D_ * D_) / 256, 256>>>(wk, p_wt);
        k_mma_gemm<<<mma_grid, 256>>>(p_ahh, p_wt, 0, p_k);
        k_cvt_W<<<(D_ * D_) / 256, 256>>>(wv, p_wt);
        k_mma_gemm<<<mma_grid, 256>>>(p_ahh, p_wt, 0, p_v);

        k_init_seg<<<ND_ / 256, 256>>>();
        k_logit<<<BE_ / 8, 256>>>(de, da, re);
        k_exp<<<(BE_ * H_) / 256, 256>>>();
        k_msg<<<BE_ / 8, 256>>>(de, da, re, out_attn + (size_t)l * BE_ * H_, write_attn);

        k_cvt_A<<<ND_ / 4 / 256, 256>>>(p_agg, p_ahh);
        k_cvt_W<<<(D_ * D_) / 256, 256>>>(wo, p_wt);
        k_mma_gemm<<<mma_grid, 256>>>(p_ahh, p_wt, hsrc, p_tmp);

        k_ln<<<N_, 256>>>(p_tmp, ln_scale + (size_t)l * D_, ln_bias + (size_t)l * D_,
                          out_reps + (size_t)l * N_ * D_, p_h,
                          (l < L_ - 1) ? 1 : 0, write_reps);
    }
    (void)in_sizes; (void)n_in; (void)out_size;
}